// round 16
// baseline (speedup 1.0000x reference)
#include <cuda_runtime.h>
#include <cuda_bf16.h>
#include <cuda_fp16.h>
#include <cstdint>
#include <math.h>

// Problem constants (B=8, H=W=128, C=384, window=8)
#define TOKENS   131072              // 8*128*128
#define CDIM     384
#define NQKV     1152
#define NWIN     2048                // 8 * 16 * 16 windows

// ---------------------------------------------------------------------------
// Scratch (allocation-free rule: __device__ globals)
// ---------------------------------------------------------------------------
__device__ __half        g_Mcat[768 * CDIM];              // [M1^T ; M2^T] fp16
__device__ float         g_w1[CDIM];                      // Wk·b_q
__device__ float         g_Bout[CDIM];                    // b_v·Wp + b_p
__device__ __half        g_xh[(size_t)TOKENS * CDIM];     // x fp16 (GEMM A)
__device__ __nv_bfloat16 g_xs[(size_t)TOKENS * 768];      // x split planes [hi|lo]
__device__ float         g_c [(size_t)TOKENS];            // S column bias
__device__ __nv_bfloat16 g_y [(size_t)TOKENS * 768];      // Y split planes [hi|lo]
__device__ __half        g_u [(size_t)TOKENS * CDIM];     // u = x·M2 fp16

__device__ __forceinline__ uint32_t smem_u32(const void* p) {
    uint32_t a;
    asm("{ .reg .u64 tmp; cvta.to.shared.u64 tmp, %1; cvt.u32.u64 %0, tmp; }"
        : "=r"(a) : "l"(p));
    return a;
}

// Split a float2 into packed bf16x2 hi and lo (residual) parts.
__device__ __forceinline__ void split2(float x, float y, uint32_t& hi, uint32_t& lo) {
    uint32_t h;
    asm("cvt.rn.bf16x2.f32 %0, %1, %2;" : "=r"(h) : "f"(y), "f"(x));
    float h0 = __uint_as_float(h << 16);
    float h1 = __uint_as_float(h & 0xffff0000u);
    float r0 = x - h0, r1 = y - h1;
    asm("cvt.rn.bf16x2.f32 %0, %1, %2;" : "=r"(lo) : "f"(r1), "f"(r0));
    hi = h;
}

// bf16 HMMA (attention S-phase)
__device__ __forceinline__ void mma16816(float* c, const uint32_t* a,
                                         uint32_t b0, uint32_t b1) {
    asm volatile(
        "mma.sync.aligned.m16n8k16.row.col.f32.bf16.bf16.f32 "
        "{%0,%1,%2,%3}, {%4,%5,%6,%7}, {%8,%9}, {%0,%1,%2,%3};\n"
        : "+f"(c[0]), "+f"(c[1]), "+f"(c[2]), "+f"(c[3])
        : "r"(a[0]), "r"(a[1]), "r"(a[2]), "r"(a[3]), "r"(b0), "r"(b1));
}

// fp16 HMMA (GEMM + attention O-phase)
__device__ __forceinline__ void mma16816h(float* c, const uint32_t* a,
                                          uint32_t b0, uint32_t b1) {
    asm volatile(
        "mma.sync.aligned.m16n8k16.row.col.f32.f16.f16.f32 "
        "{%0,%1,%2,%3}, {%4,%5,%6,%7}, {%8,%9}, {%0,%1,%2,%3};\n"
        : "+f"(c[0]), "+f"(c[1]), "+f"(c[2]), "+f"(c[3])
        : "r"(a[0]), "r"(a[1]), "r"(a[2]), "r"(a[3]), "r"(b0), "r"(b1));
}

#define LDSM_X4(r, a) \
    asm volatile("ldmatrix.sync.aligned.m8n8.x4.shared.b16 {%0,%1,%2,%3}, [%4];" \
        : "=r"((r)[0]), "=r"((r)[1]), "=r"((r)[2]), "=r"((r)[3]) : "r"(a))

#define LDSM_X4_T(r, a) \
    asm volatile("ldmatrix.sync.aligned.m8n8.x4.trans.shared.b16 {%0,%1,%2,%3}, [%4];" \
        : "=r"((r)[0]), "=r"((r)[1]), "=r"((r)[2]), "=r"((r)[3]) : "r"(a))

// ---------------------------------------------------------------------------
// Small fp32 GEMM -> fp16
// ---------------------------------------------------------------------------
__global__ __launch_bounds__(256) void small_gemm(
    const float* __restrict__ A, const float* __restrict__ B,
    __half* __restrict__ Cc, int m0out,
    int saR, int saC, int sbR, int sbC)
{
    __shared__ float As[16][68], Bs[16][68];
    const int tid = threadIdx.x;
    const int tx = tid & 15, ty = tid >> 4;
    const int bm = blockIdx.y * 64, bn = blockIdx.x * 64;
    float acc[4][4];
#pragma unroll
    for (int i = 0; i < 4; i++)
#pragma unroll
        for (int j = 0; j < 4; j++) acc[i][j] = 0.f;

    for (int k0 = 0; k0 < CDIM; k0 += 16) {
#pragma unroll
        for (int i = 0; i < 4; i++) {
            const int id = tid + i * 256;
            const int m = id & 63, k = id >> 6;
            As[k][m] = A[(size_t)(bm + m) * saR + (size_t)(k0 + k) * saC];
            Bs[k][m] = B[(size_t)(bn + m) * sbR + (size_t)(k0 + k) * sbC];
        }
        __syncthreads();
#pragma unroll
        for (int k = 0; k < 16; k++)
#pragma unroll
            for (int i = 0; i < 4; i++)
#pragma unroll
                for (int j = 0; j < 4; j++)
                    acc[i][j] += As[k][ty * 4 + i] * Bs[k][tx * 4 + j];
        __syncthreads();
    }
#pragma unroll
    for (int i = 0; i < 4; i++)
#pragma unroll
        for (int j = 0; j < 4; j++)
            Cc[(size_t)(m0out + bm + ty * 4 + i) * CDIM + bn + tx * 4 + j] =
                __float2half(acc[i][j]);
}

// ---------------------------------------------------------------------------
// Bias vectors
// ---------------------------------------------------------------------------
__global__ __launch_bounds__(256) void bias_vec(
    const float* __restrict__ w_qkv, const float* __restrict__ b_qkv,
    const float* __restrict__ w_proj, const float* __restrict__ b_proj)
{
    const int t = blockIdx.x * 256 + threadIdx.x;
    if (t < CDIM) {
        float s = 0.f;
        for (int c = 0; c < CDIM; c++)
            s += w_qkv[(size_t)t * NQKV + 384 + c] * b_qkv[c];
        g_w1[t] = s;
    } else if (t < 2 * CDIM) {
        const int n = t - CDIM;
        float s = 0.f;
        for (int c = 0; c < CDIM; c++)
            s += b_qkv[768 + c] * w_proj[(size_t)c * CDIM + n];
        g_Bout[n] = s + b_proj[n];
    }
}

// ---------------------------------------------------------------------------
// x -> fp16 (g_xh) + split-bf16 planes (g_xs) + column bias c = x·w1 (g_c)
// ---------------------------------------------------------------------------
__global__ __launch_bounds__(256) void cvt_split(const float* __restrict__ x)
{
    __shared__ float w1s[CDIM];
    for (int i = threadIdx.x; i < CDIM; i += 256) w1s[i] = g_w1[i];
    __syncthreads();

    const int row = blockIdx.x * 32 + (threadIdx.x >> 3);
    const int j   = threadIdx.x & 7;
    const float* xr = x + (size_t)row * CDIM;
    float dot = 0.f;
#pragma unroll
    for (int k = 0; k < 12; k++) {
        const int col = j * 4 + k * 32;
        float4 v = *(const float4*)(xr + col);
        __half2 a = __floats2half2_rn(v.x, v.y);
        __half2 b = __floats2half2_rn(v.z, v.w);
        *(uint2*)(g_xh + (size_t)row * CDIM + col) =
            make_uint2(*(uint32_t*)&a, *(uint32_t*)&b);
        uint32_t h0, l0, h1, l1;
        split2(v.x, v.y, h0, l0);
        split2(v.z, v.w, h1, l1);
        *(uint2*)(g_xs + (size_t)row * 768 + col)       = make_uint2(h0, h1);
        *(uint2*)(g_xs + (size_t)row * 768 + 384 + col) = make_uint2(l0, l1);
        dot += v.x * w1s[col] + v.y * w1s[col + 1]
             + v.z * w1s[col + 2] + v.w * w1s[col + 3];
    }
#pragma unroll
    for (int o = 4; o > 0; o >>= 1) dot += __shfl_down_sync(0xffffffffu, dot, o, 8);
    if (j == 0) g_c[row] = dot;
}

// ---------------------------------------------------------------------------
// Fused GEMM: [Y|u] = x(fp16) @ Mcat^T (r14, validated)
// ---------------------------------------------------------------------------
#define STAGE_BYTES 32768u
__global__ __launch_bounds__(256, 2) void gemm_fused()
{
    extern __shared__ __align__(16) char smem[];
    const uint32_t smemBase = smem_u32(smem);

    const int tid  = threadIdx.x;
    const int wid  = tid >> 5;
    const int lane = tid & 31;
    const int g    = lane >> 2;
    const int t4   = lane & 3;
    const int m0   = blockIdx.y * 128;
    const int n0   = blockIdx.x * 128;
    const int wm   = (wid & 3) * 32;
    const int wn   = (wid >> 2) * 64;

    const __half* srcs[8];
    uint32_t dsts[8];
#pragma unroll
    for (int i = 0; i < 8; i++) {
        const int id = tid + i * 256;
        const int ab = id >> 10;
        const int r  = (id >> 3) & 127;
        const int ch = id & 7;
        if (ab == 0) srcs[i] = g_xh   + (size_t)(m0 + r) * CDIM + ch * 8;
        else         srcs[i] = g_Mcat + (size_t)(n0 + r) * CDIM + ch * 8;
        dsts[i] = smemBase + (uint32_t)(ab * 16384 + r * 128 + ((ch ^ (r & 7)) * 16));
    }

#define PREFETCH(s, off) do {                                                 \
        _Pragma("unroll")                                                     \
        for (int _i = 0; _i < 8; _i++) {                                      \
            asm volatile("cp.async.cg.shared.global [%0], [%1], 16;"          \
                :: "r"(dsts[_i] + (off)), "l"(srcs[_i] + (s) * 64));          \
        }                                                                     \
        asm volatile("cp.async.commit_group;" ::: "memory");                  \
    } while (0)

    const int la = lane & 15;
    const int h  = lane >> 4;
    const int s7 = la & 7;
    uint32_t coff[4];
#pragma unroll
    for (int q = 0; q < 4; q++)
        coff[q] = (uint32_t)((((2 * q + h) ^ s7) & 7) * 16);
    const uint32_t aBase = smemBase + (uint32_t)((wm + la) * 128);
    const uint32_t bBase = smemBase + 16384 + (uint32_t)((wn + la) * 128);

    float acc[2][8][4];
#pragma unroll
    for (int mt = 0; mt < 2; mt++)
#pragma unroll
        for (int nt = 0; nt < 8; nt++)
#pragma unroll
            for (int i = 0; i < 4; i++) acc[mt][nt][i] = 0.f;

    PREFETCH(0, 0);
    PREFETCH(1, STAGE_BYTES);

#pragma unroll
    for (int s = 0; s < 6; s++) {
        asm volatile("cp.async.wait_group 1;" ::: "memory");
        __syncthreads();
        if (s < 4) PREFETCH(s + 2, ((s + 2) % 3) * STAGE_BYTES);
        else asm volatile("cp.async.commit_group;" ::: "memory");
        const uint32_t off = (s % 3) * STAGE_BYTES;

#pragma unroll
        for (int q = 0; q < 4; q++) {
            uint32_t a[2][4];
#pragma unroll
            for (int mt = 0; mt < 2; mt++)
                LDSM_X4(a[mt], aBase + off + mt * 2048 + coff[q]);
#pragma unroll
            for (int ntp = 0; ntp < 4; ntp++) {
                uint32_t b[4];
                LDSM_X4(b, bBase + off + ntp * 2048 + coff[q]);
                mma16816h(acc[0][ntp * 2],     a[0], b[0], b[2]);
                mma16816h(acc[0][ntp * 2 + 1], a[0], b[1], b[3]);
                mma16816h(acc[1][ntp * 2],     a[1], b[0], b[2]);
                mma16816h(acc[1][ntp * 2 + 1], a[1], b[1], b[3]);
            }
        }
    }
#undef PREFETCH

    __syncthreads();
    if (blockIdx.x < 3) {
        const int wi = blockIdx.x * 128;
#pragma unroll
        for (int mt = 0; mt < 2; mt++) {
            const int lr = wm + mt * 16 + g;
#pragma unroll
            for (int nt = 0; nt < 8; nt++) {
                const int cl = wn + (nt >> 1) * 16 + (nt & 1) * 8 + t4 * 2;
                uint32_t hh, ll;
                split2(acc[mt][nt][0], acc[mt][nt][1], hh, ll);
                *(uint32_t*)(smem + lr * 272 + cl * 2) = hh;
                *(uint32_t*)(smem + 34816 + lr * 272 + cl * 2) = ll;
                split2(acc[mt][nt][2], acc[mt][nt][3], hh, ll);
                *(uint32_t*)(smem + (lr + 8) * 272 + cl * 2) = hh;
                *(uint32_t*)(smem + 34816 + (lr + 8) * 272 + cl * 2) = ll;
            }
        }
        __syncthreads();
        __nv_bfloat16* gb = g_y + (size_t)m0 * 768 + wi;
#pragma unroll
        for (int i = 0; i < 16; i++) {
            const int id = tid + i * 256;
            const int t  = id >> 5;
            const int ch = id & 31;
            *(uint2*)(gb + (size_t)t * 768 + ch * 4) =
                *(uint2*)(smem + t * 272 + ch * 8);
            *(uint2*)(gb + (size_t)t * 768 + 384 + ch * 4) =
                *(uint2*)(smem + 34816 + t * 272 + ch * 8);
        }
    } else {
        const int wi = (blockIdx.x - 3) * 128;
#pragma unroll
        for (int mt = 0; mt < 2; mt++) {
            const int lr = wm + mt * 16 + g;
#pragma unroll
            for (int nt = 0; nt < 8; nt++) {
                const int cl = wn + (nt >> 1) * 16 + (nt & 1) * 8 + t4 * 2;
                __half2 h0 = __floats2half2_rn(acc[mt][nt][0], acc[mt][nt][1]);
                __half2 h1 = __floats2half2_rn(acc[mt][nt][2], acc[mt][nt][3]);
                *(uint32_t*)(smem + lr * 272 + cl * 2) = *(uint32_t*)&h0;
                *(uint32_t*)(smem + (lr + 8) * 272 + cl * 2) = *(uint32_t*)&h1;
            }
        }
        __syncthreads();
        __half* gv = g_u + (size_t)m0 * CDIM + wi;
#pragma unroll
        for (int i = 0; i < 16; i++) {
            const int id = tid + i * 256;
            const int t  = id >> 5;
            const int ch = id & 31;
            *(uint2*)(gv + (size_t)t * CDIM + ch * 4) =
                *(uint2*)(smem + t * 272 + ch * 8);
        }
    }
}

// ---------------------------------------------------------------------------
// Window attention v6: 3-stage pipelines (S and O), 128-thread softmax.
//   S stages @0/16384/32768 (4 planes x 4KB each, 64B rows, sw (t>>1)&3);
//   P fp16 @49152 (128B rows); Ss fp32 overlays stage0; tok @57344, cw @57600.
// ---------------------------------------------------------------------------
#define ATTN_SMEM 57856
__global__ __launch_bounds__(128, 4) void window_attn(float* __restrict__ out)
{
    extern __shared__ __align__(16) char asm_[];
    const uint32_t sb = smem_u32(asm_);
    int* tok = (int*)(asm_ + 57344);
    float* cw = (float*)(asm_ + 57600);
    float (*Ss)[65] = (float(*)[65])asm_;

    const int gb = blockIdx.x;
    const int b = gb >> 8, win = gb & 255, wy = win >> 4, wx = win & 15;
    const int tid = threadIdx.x;
    if (tid < 64) {
        int py = tid >> 3, px = tid & 7;
        tok[tid] = b * 16384 + (wy * 8 + py) * 128 + (wx * 8 + px);
    }
    __syncthreads();
    if (tid < 64) cw[tid] = g_c[tok[tid]];

    const int wid = tid >> 5, lane = tid & 31;
    const int g = lane >> 2, t4 = lane & 3;
    const int la = lane & 15, lh = lane >> 4;

    uint32_t coffS[2];
#pragma unroll
    for (int q = 0; q < 2; q++)
        coffS[q] = (uint32_t)((((2 * q + lh) ^ ((la >> 1) & 3)) & 3) * 16);
    uint32_t coffO[4];
#pragma unroll
    for (int q = 0; q < 4; q++)
        coffO[q] = (uint32_t)((((2 * q + lh) ^ (la & 7)) & 7) * 16);

    // ---- S-phase loaders ----
    const __nv_bfloat16* sQK[8];
    uint32_t dQK[8];
#pragma unroll
    for (int i = 0; i < 8; i++) {
        const int id = tid + i * 128;          // < 1024
        const int p  = id >> 8;
        const int t  = (id >> 2) & 63;
        const int ci = id & 3;
        sQK[i] = (p < 2 ? g_y + (size_t)tok[t] * 768 + p * 384
                        : g_xs + (size_t)tok[t] * 768 + (p - 2) * 384) + ci * 8;
        dQK[i] = sb + (uint32_t)(p * 4096 + t * 64 + (((ci ^ ((t >> 1) & 3)) & 3) * 16));
    }

#define PREF_QK(cc) do {                                                      \
        const uint32_t _o = ((cc) % 3) * 16384u;                              \
        _Pragma("unroll")                                                     \
        for (int _i = 0; _i < 8; _i++) {                                      \
            asm volatile("cp.async.cg.shared.global [%0], [%1], 16;"          \
                :: "r"(dQK[_i] + _o), "l"(sQK[_i] + (cc) * 32));              \
        }                                                                     \
        asm volatile("cp.async.commit_group;" ::: "memory");                  \
    } while (0)

    float accS[8][4];
#pragma unroll
    for (int nt = 0; nt < 8; nt++)
#pragma unroll
        for (int i = 0; i < 4; i++) accS[nt][i] = 0.f;

    PREF_QK(0);
    PREF_QK(1);

#pragma unroll
    for (int cc = 0; cc < 12; cc++) {
        asm volatile("cp.async.wait_group 1;" ::: "memory");
        __syncthreads();
        if (cc < 10) PREF_QK(cc + 2);
        else asm volatile("cp.async.commit_group;" ::: "memory");
        const uint32_t st = (cc % 3) * 16384u;
        const uint32_t aYh = sb + st + (uint32_t)((wid * 16 + la) * 64);
        const uint32_t aYl = aYh + 4096;
        const uint32_t bXh = sb + st + 8192 + (uint32_t)(la * 64);
        const uint32_t bXl = bXh + 4096;
#pragma unroll
        for (int kt = 0; kt < 2; kt++) {
            uint32_t yh[4], yl[4];
            LDSM_X4(yh, aYh + coffS[kt]);
            LDSM_X4(yl, aYl + coffS[kt]);
#pragma unroll
            for (int ntp = 0; ntp < 4; ntp++) {
                uint32_t xh[4], xl[4];
                LDSM_X4(xh, bXh + ntp * 1024 + coffS[kt]);
                LDSM_X4(xl, bXl + ntp * 1024 + coffS[kt]);
                mma16816(accS[ntp * 2],     yh, xh[0], xh[2]);
                mma16816(accS[ntp * 2 + 1], yh, xh[1], xh[3]);
                mma16816(accS[ntp * 2],     yl, xh[0], xh[2]);
                mma16816(accS[ntp * 2 + 1], yl, xh[1], xh[3]);
                mma16816(accS[ntp * 2],     yh, xl[0], xl[2]);
                mma16816(accS[ntp * 2 + 1], yh, xl[1], xl[3]);
            }
        }
    }
#undef PREF_QK
    __syncthreads();

    // ---- S -> Ss (fp32, overlays stage region) ----
    {
        const int r0 = wid * 16 + g;
#pragma unroll
        for (int nt = 0; nt < 8; nt++) {
            const int col = nt * 8 + t4 * 2;
            Ss[r0][col]         = accS[nt][0];
            Ss[r0][col + 1]     = accS[nt][1];
            Ss[r0 + 8][col]     = accS[nt][2];
            Ss[r0 + 8][col + 1] = accS[nt][3];
        }
    }
    __syncthreads();

    // ---- softmax on 128 threads: thread pair (2r, 2r+1) per row ----
    {
        const int row = tid >> 1;
        const int cb  = (tid & 1) * 32;
        float m = -1e30f;
#pragma unroll 8
        for (int j = 0; j < 32; j++) m = fmaxf(m, Ss[row][cb + j] + cw[cb + j]);
        m = fmaxf(m, __shfl_xor_sync(0xffffffffu, m, 1));
        float s = 0.f;
#pragma unroll 8
        for (int j = 0; j < 32; j++) {
            float e = expf(Ss[row][cb + j] + cw[cb + j] - m);
            Ss[row][cb + j] = e;
            s += e;
        }
        s += __shfl_xor_sync(0xffffffffu, s, 1);
        float inv = 1.f / s;
        __syncwarp();
#pragma unroll 8
        for (int j = 0; j < 32; j += 2) {
            __half2 p2 = __floats2half2_rn(Ss[row][cb + j] * inv,
                                           Ss[row][cb + j + 1] * inv);
            const int w = (cb + j) >> 1;
            const uint32_t off = (uint32_t)(row * 128 +
                (((w >> 2) ^ (row & 7)) * 16) + (w & 3) * 4);
            *(uint32_t*)(asm_ + 49152 + off) = *(uint32_t*)&p2;
        }
    }
    __syncthreads();

    // ---- P fragments (fp16, loop-invariant; 128B rows -> coffO) ----
    uint32_t ph[4][4];
    const uint32_t aPh = sb + 49152 + (uint32_t)((wid * 16 + la) * 128);
#pragma unroll
    for (int kt = 0; kt < 4; kt++)
        LDSM_X4(ph[kt], aPh + coffO[kt]);
    const int tr0 = tok[wid * 16 + g];
    const int tr1 = tok[wid * 16 + g + 8];

    // ---- O-phase loaders: u fp16, 64-col chunks (8KB) in 3 stage slots ----
    const __half* sV[4];
    uint32_t dV[4];
#pragma unroll
    for (int i = 0; i < 4; i++) {
        const int id = tid + i * 128;          // < 512
        const int t  = id >> 3;
        const int ci = id & 7;
        sV[i] = g_u + (size_t)tok[t] * CDIM + ci * 8;
        dV[i] = sb + (uint32_t)(t * 128 + ((ci ^ (t & 7)) * 16));
    }

#define PREF_V(co) do {                                                       \
        const uint32_t _o = ((co) % 3) * 16384u;                              \
        _Pragma("unroll")                                                     \
        for (int _i = 0; _i < 4; _i++) {                                      \
            asm volatile("cp.async.cg.shared.global [%0], [%1], 16;"          \
                :: "r"(dV[_i] + _o), "l"(sV[_i] + (co) * 64));                \
        }                                                                     \
        asm volatile("cp.async.commit_group;" ::: "memory");                  \
    } while (0)

    PREF_V(0);
    PREF_V(1);

    const uint32_t vbase = sb + (uint32_t)(((((lane >> 3) & 1) * 8) + (lane & 7)) * 128);

#pragma unroll
    for (int co = 0; co < 6; co++) {
        asm volatile("cp.async.wait_group 1;" ::: "memory");
        __syncthreads();
        if (co < 4) PREF_V(co + 2);
        else asm volatile("cp.async.commit_group;" ::: "memory");
        const uint32_t bVh = vbase + (co % 3) * 16384u;

        float accO[8][4];
#pragma unroll
        for (int nt = 0; nt < 8; nt++)
#pragma unroll
            for (int i = 0; i < 4; i++) accO[nt][i] = 0.f;

#pragma unroll
        for (int kt = 0; kt < 4; kt++) {
#pragma unroll
            for (int ntp = 0; ntp < 4; ntp++) {
                uint32_t vh[4];
                LDSM_X4_T(vh, bVh + kt * 2048 + coffO[ntp]);
                mma16816h(accO[ntp * 2],     ph[kt], vh[0], vh[1]);
                mma16816h(accO[ntp * 2 + 1], ph[kt], vh[2], vh[3]);
            }
        }
#pragma unroll
        for (int nt = 0; nt < 8; nt++) {
            const int col = co * 64 + nt * 8 + t4 * 2;
            float2 bo = *(const float2*)(g_Bout + col);
            *(float2*)(out + (size_t)tr0 * CDIM + col) =
                make_float2(accO[nt][0] + bo.x, accO[nt][1] + bo.y);
            *(float2*)(out + (size_t)tr1 * CDIM + col) =
                make_float2(accO[nt][2] + bo.x, accO[nt][3] + bo.y);
        }
    }
#undef PREF_V
}

// ---------------------------------------------------------------------------
extern "C" void kernel_launch(void* const* d_in, const int* in_sizes, int n_in,
                              void* d_out, int out_size)
{
    const float* x      = (const float*)d_in[0];
    const float* w_qkv  = (const float*)d_in[1];
    const float* b_qkv  = (const float*)d_in[2];
    const float* w_proj = (const float*)d_in[3];
    const float* b_proj = (const float*)d_in[4];
    float* out = (float*)d_out;

    __half* mcat = nullptr;
    cudaGetSymbolAddress((void**)&mcat, g_Mcat);

    cudaFuncSetAttribute(gemm_fused, cudaFuncAttributeMaxDynamicSharedMemorySize,
                         3 * STAGE_BYTES);
    cudaFuncSetAttribute(window_attn, cudaFuncAttributeMaxDynamicSharedMemorySize,
                         ATTN_SMEM);

    bias_vec<<<3, 256>>>(w_qkv, b_qkv, w_proj, b_proj);
    small_gemm<<<dim3(6, 6), 256>>>(w_qkv + 384, w_qkv, mcat, 0,
                                    NQKV, 1, NQKV, 1);
    small_gemm<<<dim3(6, 6), 256>>>(w_proj, w_qkv + 768, mcat, 384,
                                    1, CDIM, NQKV, 1);

    cvt_split<<<TOKENS / 32, 256>>>(x);

    gemm_fused<<<dim3(6, TOKENS / 128), 256, 3 * STAGE_BYTES>>>();

    window_attn<<<NWIN, 128, ATTN_SMEM>>>(out);
}

// round 17
// speedup vs baseline: 1.1072x; 1.1072x over previous
#include <cuda_runtime.h>
#include <cuda_bf16.h>
#include <cuda_fp16.h>
#include <cstdint>
#include <math.h>

// Problem constants (B=8, H=W=128, C=384, window=8)
#define TOKENS   131072              // 8*128*128
#define CDIM     384
#define NQKV     1152
#define NWIN     2048                // 8 * 16 * 16 windows

// ---------------------------------------------------------------------------
// Scratch (allocation-free rule: __device__ globals)
// ---------------------------------------------------------------------------
__device__ __half g_Mcat[768 * CDIM];             // [M1^T ; M2^T] fp16
__device__ float  g_w1[CDIM];                     // Wk·b_q
__device__ float  g_Bout[CDIM];                   // b_v·Wp + b_p
__device__ __half g_xh[(size_t)TOKENS * CDIM];    // x fp16 (GEMM A + S B-operand)
__device__ float  g_c [(size_t)TOKENS];           // S column bias
__device__ __half g_y [(size_t)TOKENS * 768];     // Y split-fp16 planes [hi|lo]
__device__ __half g_u [(size_t)TOKENS * CDIM];    // u = x·M2 fp16

__device__ __forceinline__ uint32_t smem_u32(const void* p) {
    uint32_t a;
    asm("{ .reg .u64 tmp; cvta.to.shared.u64 tmp, %1; cvt.u32.u64 %0, tmp; }"
        : "=r"(a) : "l"(p));
    return a;
}

// Split a float2 into packed fp16x2 hi and lo (residual) parts.
__device__ __forceinline__ void splith2(float x, float y, uint32_t& hi, uint32_t& lo) {
    __half2 h = __floats2half2_rn(x, y);
    float hx = __half2float(__low2half(h));
    float hy = __half2float(__high2half(h));
    __half2 l = __floats2half2_rn(x - hx, y - hy);
    hi = *(uint32_t*)&h;
    lo = *(uint32_t*)&l;
}

// fp16 HMMA
__device__ __forceinline__ void mma16816h(float* c, const uint32_t* a,
                                          uint32_t b0, uint32_t b1) {
    asm volatile(
        "mma.sync.aligned.m16n8k16.row.col.f32.f16.f16.f32 "
        "{%0,%1,%2,%3}, {%4,%5,%6,%7}, {%8,%9}, {%0,%1,%2,%3};\n"
        : "+f"(c[0]), "+f"(c[1]), "+f"(c[2]), "+f"(c[3])
        : "r"(a[0]), "r"(a[1]), "r"(a[2]), "r"(a[3]), "r"(b0), "r"(b1));
}

#define LDSM_X4(r, a) \
    asm volatile("ldmatrix.sync.aligned.m8n8.x4.shared.b16 {%0,%1,%2,%3}, [%4];" \
        : "=r"((r)[0]), "=r"((r)[1]), "=r"((r)[2]), "=r"((r)[3]) : "r"(a))

#define LDSM_X4_T(r, a) \
    asm volatile("ldmatrix.sync.aligned.m8n8.x4.trans.shared.b16 {%0,%1,%2,%3}, [%4];" \
        : "=r"((r)[0]), "=r"((r)[1]), "=r"((r)[2]), "=r"((r)[3]) : "r"(a))

// ---------------------------------------------------------------------------
// Small fp32 GEMM -> fp16 (M1^T / M2^T precompute)
// ---------------------------------------------------------------------------
__global__ __launch_bounds__(256) void small_gemm(
    const float* __restrict__ A, const float* __restrict__ B,
    __half* __restrict__ Cc, int m0out,
    int saR, int saC, int sbR, int sbC)
{
    __shared__ float As[16][68], Bs[16][68];
    const int tid = threadIdx.x;
    const int tx = tid & 15, ty = tid >> 4;
    const int bm = blockIdx.y * 64, bn = blockIdx.x * 64;
    float acc[4][4];
#pragma unroll
    for (int i = 0; i < 4; i++)
#pragma unroll
        for (int j = 0; j < 4; j++) acc[i][j] = 0.f;

    for (int k0 = 0; k0 < CDIM; k0 += 16) {
#pragma unroll
        for (int i = 0; i < 4; i++) {
            const int id = tid + i * 256;
            const int m = id & 63, k = id >> 6;
            As[k][m] = A[(size_t)(bm + m) * saR + (size_t)(k0 + k) * saC];
            Bs[k][m] = B[(size_t)(bn + m) * sbR + (size_t)(k0 + k) * sbC];
        }
        __syncthreads();
#pragma unroll
        for (int k = 0; k < 16; k++)
#pragma unroll
            for (int i = 0; i < 4; i++)
#pragma unroll
                for (int j = 0; j < 4; j++)
                    acc[i][j] += As[k][ty * 4 + i] * Bs[k][tx * 4 + j];
        __syncthreads();
    }
#pragma unroll
    for (int i = 0; i < 4; i++)
#pragma unroll
        for (int j = 0; j < 4; j++)
            Cc[(size_t)(m0out + bm + ty * 4 + i) * CDIM + bn + tx * 4 + j] =
                __float2half(acc[i][j]);
}

// ---------------------------------------------------------------------------
// Bias vectors
// ---------------------------------------------------------------------------
__global__ __launch_bounds__(256) void bias_vec(
    const float* __restrict__ w_qkv, const float* __restrict__ b_qkv,
    const float* __restrict__ w_proj, const float* __restrict__ b_proj)
{
    const int t = blockIdx.x * 256 + threadIdx.x;
    if (t < CDIM) {
        float s = 0.f;
        for (int c = 0; c < CDIM; c++)
            s += w_qkv[(size_t)t * NQKV + 384 + c] * b_qkv[c];
        g_w1[t] = s;
    } else if (t < 2 * CDIM) {
        const int n = t - CDIM;
        float s = 0.f;
        for (int c = 0; c < CDIM; c++)
            s += b_qkv[768 + c] * w_proj[(size_t)c * CDIM + n];
        g_Bout[n] = s + b_proj[n];
    }
}

// ---------------------------------------------------------------------------
// x -> fp16 (g_xh) + column bias c = x·w1 (g_c)   [xs planes eliminated]
// ---------------------------------------------------------------------------
__global__ __launch_bounds__(256) void cvt_split(const float* __restrict__ x)
{
    __shared__ float w1s[CDIM];
    for (int i = threadIdx.x; i < CDIM; i += 256) w1s[i] = g_w1[i];
    __syncthreads();

    const int row = blockIdx.x * 32 + (threadIdx.x >> 3);
    const int j   = threadIdx.x & 7;
    const float* xr = x + (size_t)row * CDIM;
    float dot = 0.f;
#pragma unroll
    for (int k = 0; k < 12; k++) {
        const int col = j * 4 + k * 32;
        float4 v = *(const float4*)(xr + col);
        __half2 a = __floats2half2_rn(v.x, v.y);
        __half2 b = __floats2half2_rn(v.z, v.w);
        *(uint2*)(g_xh + (size_t)row * CDIM + col) =
            make_uint2(*(uint32_t*)&a, *(uint32_t*)&b);
        dot += v.x * w1s[col] + v.y * w1s[col + 1]
             + v.z * w1s[col + 2] + v.w * w1s[col + 3];
    }
#pragma unroll
    for (int o = 4; o > 0; o >>= 1) dot += __shfl_down_sync(0xffffffffu, dot, o, 8);
    if (j == 0) g_c[row] = dot;
}

// ---------------------------------------------------------------------------
// Fused GEMM: [Y|u] = x(fp16) @ Mcat^T (validated core; Y epilogue split-fp16)
// ---------------------------------------------------------------------------
#define STAGE_BYTES 32768u
__global__ __launch_bounds__(256, 2) void gemm_fused()
{
    extern __shared__ __align__(16) char smem[];
    const uint32_t smemBase = smem_u32(smem);

    const int tid  = threadIdx.x;
    const int wid  = tid >> 5;
    const int lane = tid & 31;
    const int g    = lane >> 2;
    const int t4   = lane & 3;
    const int m0   = blockIdx.y * 128;
    const int n0   = blockIdx.x * 128;
    const int wm   = (wid & 3) * 32;
    const int wn   = (wid >> 2) * 64;

    const __half* srcs[8];
    uint32_t dsts[8];
#pragma unroll
    for (int i = 0; i < 8; i++) {
        const int id = tid + i * 256;
        const int ab = id >> 10;
        const int r  = (id >> 3) & 127;
        const int ch = id & 7;
        if (ab == 0) srcs[i] = g_xh   + (size_t)(m0 + r) * CDIM + ch * 8;
        else         srcs[i] = g_Mcat + (size_t)(n0 + r) * CDIM + ch * 8;
        dsts[i] = smemBase + (uint32_t)(ab * 16384 + r * 128 + ((ch ^ (r & 7)) * 16));
    }

#define PREFETCH(s, off) do {                                                 \
        _Pragma("unroll")                                                     \
        for (int _i = 0; _i < 8; _i++) {                                      \
            asm volatile("cp.async.cg.shared.global [%0], [%1], 16;"          \
                :: "r"(dsts[_i] + (off)), "l"(srcs[_i] + (s) * 64));          \
        }                                                                     \
        asm volatile("cp.async.commit_group;" ::: "memory");                  \
    } while (0)

    const int la = lane & 15;
    const int h  = lane >> 4;
    const int s7 = la & 7;
    uint32_t coff[4];
#pragma unroll
    for (int q = 0; q < 4; q++)
        coff[q] = (uint32_t)((((2 * q + h) ^ s7) & 7) * 16);
    const uint32_t aBase = smemBase + (uint32_t)((wm + la) * 128);
    const uint32_t bBase = smemBase + 16384 + (uint32_t)((wn + la) * 128);

    float acc[2][8][4];
#pragma unroll
    for (int mt = 0; mt < 2; mt++)
#pragma unroll
        for (int nt = 0; nt < 8; nt++)
#pragma unroll
            for (int i = 0; i < 4; i++) acc[mt][nt][i] = 0.f;

    PREFETCH(0, 0);
    PREFETCH(1, STAGE_BYTES);

#pragma unroll
    for (int s = 0; s < 6; s++) {
        asm volatile("cp.async.wait_group 1;" ::: "memory");
        __syncthreads();
        if (s < 4) PREFETCH(s + 2, ((s + 2) % 3) * STAGE_BYTES);
        else asm volatile("cp.async.commit_group;" ::: "memory");
        const uint32_t off = (s % 3) * STAGE_BYTES;

#pragma unroll
        for (int q = 0; q < 4; q++) {
            uint32_t a[2][4];
#pragma unroll
            for (int mt = 0; mt < 2; mt++)
                LDSM_X4(a[mt], aBase + off + mt * 2048 + coff[q]);
#pragma unroll
            for (int ntp = 0; ntp < 4; ntp++) {
                uint32_t b[4];
                LDSM_X4(b, bBase + off + ntp * 2048 + coff[q]);
                mma16816h(acc[0][ntp * 2],     a[0], b[0], b[2]);
                mma16816h(acc[0][ntp * 2 + 1], a[0], b[1], b[3]);
                mma16816h(acc[1][ntp * 2],     a[1], b[0], b[2]);
                mma16816h(acc[1][ntp * 2 + 1], a[1], b[1], b[3]);
            }
        }
    }
#undef PREFETCH

    __syncthreads();
    if (blockIdx.x < 3) {
        // Y -> split-fp16 planes
        const int wi = blockIdx.x * 128;
#pragma unroll
        for (int mt = 0; mt < 2; mt++) {
            const int lr = wm + mt * 16 + g;
#pragma unroll
            for (int nt = 0; nt < 8; nt++) {
                const int cl = wn + (nt >> 1) * 16 + (nt & 1) * 8 + t4 * 2;
                uint32_t hh, ll;
                splith2(acc[mt][nt][0], acc[mt][nt][1], hh, ll);
                *(uint32_t*)(smem + lr * 272 + cl * 2) = hh;
                *(uint32_t*)(smem + 34816 + lr * 272 + cl * 2) = ll;
                splith2(acc[mt][nt][2], acc[mt][nt][3], hh, ll);
                *(uint32_t*)(smem + (lr + 8) * 272 + cl * 2) = hh;
                *(uint32_t*)(smem + 34816 + (lr + 8) * 272 + cl * 2) = ll;
            }
        }
        __syncthreads();
        __half* gb = g_y + (size_t)m0 * 768 + wi;
#pragma unroll
        for (int i = 0; i < 16; i++) {
            const int id = tid + i * 256;
            const int t  = id >> 5;
            const int ch = id & 31;
            *(uint2*)(gb + (size_t)t * 768 + ch * 4) =
                *(uint2*)(smem + t * 272 + ch * 8);
            *(uint2*)(gb + (size_t)t * 768 + 384 + ch * 4) =
                *(uint2*)(smem + 34816 + t * 272 + ch * 8);
        }
    } else {
        const int wi = (blockIdx.x - 3) * 128;
#pragma unroll
        for (int mt = 0; mt < 2; mt++) {
            const int lr = wm + mt * 16 + g;
#pragma unroll
            for (int nt = 0; nt < 8; nt++) {
                const int cl = wn + (nt >> 1) * 16 + (nt & 1) * 8 + t4 * 2;
                __half2 h0 = __floats2half2_rn(acc[mt][nt][0], acc[mt][nt][1]);
                __half2 h1 = __floats2half2_rn(acc[mt][nt][2], acc[mt][nt][3]);
                *(uint32_t*)(smem + lr * 272 + cl * 2) = *(uint32_t*)&h0;
                *(uint32_t*)(smem + (lr + 8) * 272 + cl * 2) = *(uint32_t*)&h1;
            }
        }
        __syncthreads();
        __half* gv = g_u + (size_t)m0 * CDIM + wi;
#pragma unroll
        for (int i = 0; i < 16; i++) {
            const int id = tid + i * 256;
            const int t  = id >> 5;
            const int ch = id & 31;
            *(uint2*)(gv + (size_t)t * CDIM + ch * 4) =
                *(uint2*)(smem + t * 272 + ch * 8);
        }
    }
}

// ---------------------------------------------------------------------------
// Window attention v7: S = (Yh+Yl)·x^T (2-pass split-fp16 x fp16), fp32 softmax,
// O = P·u (fp16) -> d_out.  3 planes/stage (12KB), 2 stages; P @24576;
// tok @32768, cw @33024.  4 blocks/SM.
// ---------------------------------------------------------------------------
#define ATTN_SMEM 33280
__global__ __launch_bounds__(128, 4) void window_attn(float* __restrict__ out)
{
    extern __shared__ __align__(16) char asm_[];
    const uint32_t sb = smem_u32(asm_);
    int* tok = (int*)(asm_ + 32768);
    float* cw = (float*)(asm_ + 33024);
    float (*Ss)[65] = (float(*)[65])asm_;

    const int gb = blockIdx.x;
    const int b = gb >> 8, win = gb & 255, wy = win >> 4, wx = win & 15;
    const int tid = threadIdx.x;
    if (tid < 64) {
        int py = tid >> 3, px = tid & 7;
        tok[tid] = b * 16384 + (wy * 8 + py) * 128 + (wx * 8 + px);
    }
    __syncthreads();
    if (tid < 64) cw[tid] = g_c[tok[tid]];

    const int wid = tid >> 5, lane = tid & 31;
    const int g = lane >> 2, t4 = lane & 3;
    const int la = lane & 15, lh = lane >> 4;

    uint32_t coffS[2];
#pragma unroll
    for (int q = 0; q < 2; q++)
        coffS[q] = (uint32_t)((((2 * q + lh) ^ ((la >> 1) & 3)) & 3) * 16);
    uint32_t coffO[4];
#pragma unroll
    for (int q = 0; q < 4; q++)
        coffO[q] = (uint32_t)((((2 * q + lh) ^ (la & 7)) & 7) * 16);

    // ---- S-phase loaders: 3 planes (Yh, Yl, xh) x 64 tok x 4 chunks = 768 ----
    const __half* sQK[6];
    uint32_t dQK[6];
#pragma unroll
    for (int i = 0; i < 6; i++) {
        const int id = tid + i * 128;          // < 768
        const int p  = id >> 8;
        const int t  = (id >> 2) & 63;
        const int ci = id & 3;
        sQK[i] = (p < 2 ? g_y + (size_t)tok[t] * 768 + p * 384
                        : g_xh + (size_t)tok[t] * CDIM) + ci * 8;
        dQK[i] = sb + (uint32_t)(p * 4096 + t * 64 + (((ci ^ ((t >> 1) & 3)) & 3) * 16));
    }

#define PREF_QK(cc) do {                                                      \
        const uint32_t _o = ((cc) & 1) * 12288u;                              \
        _Pragma("unroll")                                                     \
        for (int _i = 0; _i < 6; _i++) {                                      \
            asm volatile("cp.async.cg.shared.global [%0], [%1], 16;"          \
                :: "r"(dQK[_i] + _o), "l"(sQK[_i] + (cc) * 32));              \
        }                                                                     \
        asm volatile("cp.async.commit_group;" ::: "memory");                  \
    } while (0)

    float accS[8][4];
#pragma unroll
    for (int nt = 0; nt < 8; nt++)
#pragma unroll
        for (int i = 0; i < 4; i++) accS[nt][i] = 0.f;

    PREF_QK(0);

#pragma unroll
    for (int cc = 0; cc < 12; cc++) {
        asm volatile("cp.async.wait_group 0;" ::: "memory");
        __syncthreads();
        if (cc < 11) PREF_QK(cc + 1);
        const uint32_t st = (cc & 1) * 12288u;
        const uint32_t aYh = sb + st + (uint32_t)((wid * 16 + la) * 64);
        const uint32_t aYl = aYh + 4096;
        const uint32_t bXh = sb + st + 8192 + (uint32_t)(la * 64);
#pragma unroll
        for (int kt = 0; kt < 2; kt++) {
            uint32_t yh[4], yl[4];
            LDSM_X4(yh, aYh + coffS[kt]);
            LDSM_X4(yl, aYl + coffS[kt]);
#pragma unroll
            for (int ntp = 0; ntp < 4; ntp++) {
                uint32_t xh[4];
                LDSM_X4(xh, bXh + ntp * 1024 + coffS[kt]);
                mma16816h(accS[ntp * 2],     yh, xh[0], xh[2]);
                mma16816h(accS[ntp * 2 + 1], yh, xh[1], xh[3]);
                mma16816h(accS[ntp * 2],     yl, xh[0], xh[2]);
                mma16816h(accS[ntp * 2 + 1], yl, xh[1], xh[3]);
            }
        }
    }
#undef PREF_QK
    __syncthreads();

    // ---- S -> Ss (fp32) ----
    {
        const int r0 = wid * 16 + g;
#pragma unroll
        for (int nt = 0; nt < 8; nt++) {
            const int col = nt * 8 + t4 * 2;
            Ss[r0][col]         = accS[nt][0];
            Ss[r0][col + 1]     = accS[nt][1];
            Ss[r0 + 8][col]     = accS[nt][2];
            Ss[r0 + 8][col + 1] = accS[nt][3];
        }
    }
    __syncthreads();

    // ---- softmax (fp32, +col bias) + P -> fp16 plane @24576 ----
    if (tid < 64) {
        float m = -1e30f;
#pragma unroll 8
        for (int j = 0; j < 64; j++) m = fmaxf(m, Ss[tid][j] + cw[j]);
        float s = 0.f;
#pragma unroll 8
        for (int j = 0; j < 64; j++) {
            float e = expf(Ss[tid][j] + cw[j] - m);
            Ss[tid][j] = e;
            s += e;
        }
        float inv = 1.f / s;
#pragma unroll 8
        for (int j = 0; j < 64; j += 2) {
            __half2 p2 = __floats2half2_rn(Ss[tid][j] * inv, Ss[tid][j + 1] * inv);
            const int w = j >> 1;
            const uint32_t off = (uint32_t)(tid * 128 +
                (((w >> 2) ^ (tid & 7)) * 16) + (w & 3) * 4);
            *(uint32_t*)(asm_ + 24576 + off) = *(uint32_t*)&p2;
        }
    }
    __syncthreads();

    // ---- P fragments (fp16, loop-invariant; 128B rows) ----
    uint32_t ph[4][4];
    const uint32_t aPh = sb + 24576 + (uint32_t)((wid * 16 + la) * 128);
#pragma unroll
    for (int kt = 0; kt < 4; kt++)
        LDSM_X4(ph[kt], aPh + coffO[kt]);
    const int tr0 = tok[wid * 16 + g];
    const int tr1 = tok[wid * 16 + g + 8];

    // ---- O-phase loaders: u fp16, 64-col chunks (8KB) in the 12KB stages ----
    const __half* sV[4];
    uint32_t dV[4];
#pragma unroll
    for (int i = 0; i < 4; i++) {
        const int id = tid + i * 128;          // < 512
        const int t  = id >> 3;
        const int ci = id & 7;
        sV[i] = g_u + (size_t)tok[t] * CDIM + ci * 8;
        dV[i] = sb + (uint32_t)(t * 128 + ((ci ^ (t & 7)) * 16));
    }

#define PREF_V(co) do {                                                       \
        const uint32_t _o = ((co) & 1) * 12288u;                              \
        _Pragma("unroll")                                                     \
        for (int _i = 0; _i < 4; _i++) {                                      \
            asm volatile("cp.async.cg.shared.global [%0], [%1], 16;"          \
                :: "r"(dV[_i] + _o), "l"(sV[_i] + (co) * 64));                \
        }                                                                     \
        asm volatile("cp.async.commit_group;" ::: "memory");                  \
    } while (0)

    PREF_V(0);

    const uint32_t vbase = sb + (uint32_t)(((((lane >> 3) & 1) * 8) + (lane & 7)) * 128);

#pragma unroll
    for (int co = 0; co < 6; co++) {
        asm volatile("cp.async.wait_group 0;" ::: "memory");
        __syncthreads();
        if (co < 5) PREF_V(co + 1);
        const uint32_t bVh = vbase + (co & 1) * 12288u;

        float accO[8][4];
#pragma unroll
        for (int nt = 0; nt < 8; nt++)
#pragma unroll
            for (int i = 0; i < 4; i++) accO[nt][i] = 0.f;

#pragma unroll
        for (int kt = 0; kt < 4; kt++) {
#pragma unroll
            for (int ntp = 0; ntp < 4; ntp++) {
                uint32_t vh[4];
                LDSM_X4_T(vh, bVh + kt * 2048 + coffO[ntp]);
                mma16816h(accO[ntp * 2],     ph[kt], vh[0], vh[1]);
                mma16816h(accO[ntp * 2 + 1], ph[kt], vh[2], vh[3]);
            }
        }
#pragma unroll
        for (int nt = 0; nt < 8; nt++) {
            const int col = co * 64 + nt * 8 + t4 * 2;
            float2 bo = *(const float2*)(g_Bout + col);
            *(float2*)(out + (size_t)tr0 * CDIM + col) =
                make_float2(accO[nt][0] + bo.x, accO[nt][1] + bo.y);
            *(float2*)(out + (size_t)tr1 * CDIM + col) =
                make_float2(accO[nt][2] + bo.x, accO[nt][3] + bo.y);
        }
    }
#undef PREF_V
}

// ---------------------------------------------------------------------------
extern "C" void kernel_launch(void* const* d_in, const int* in_sizes, int n_in,
                              void* d_out, int out_size)
{
    const float* x      = (const float*)d_in[0];
    const float* w_qkv  = (const float*)d_in[1];
    const float* b_qkv  = (const float*)d_in[2];
    const float* w_proj = (const float*)d_in[3];
    const float* b_proj = (const float*)d_in[4];
    float* out = (float*)d_out;

    __half* mcat = nullptr;
    cudaGetSymbolAddress((void**)&mcat, g_Mcat);

    cudaFuncSetAttribute(gemm_fused, cudaFuncAttributeMaxDynamicSharedMemorySize,
                         3 * STAGE_BYTES);
    cudaFuncSetAttribute(window_attn, cudaFuncAttributeMaxDynamicSharedMemorySize,
                         ATTN_SMEM);

    bias_vec<<<3, 256>>>(w_qkv, b_qkv, w_proj, b_proj);
    small_gemm<<<dim3(6, 6), 256>>>(w_qkv + 384, w_qkv, mcat, 0,
                                    NQKV, 1, NQKV, 1);
    small_gemm<<<dim3(6, 6), 256>>>(w_proj, w_qkv + 768, mcat, 384,
                                    1, CDIM, NQKV, 1);

    cvt_split<<<TOKENS / 32, 256>>>(x);

    gemm_fused<<<dim3(6, TOKENS / 128), 256, 3 * STAGE_BYTES>>>();

    window_attn<<<NWIN, 128, ATTN_SMEM>>>(out);
}